// round 16
// baseline (speedup 1.0000x reference)
#include <cuda_runtime.h>
#include <cuda_fp16.h>
#include <math.h>
#include <cstdint>

// ---------------- problem constants ----------------
constexpr int NH = 16, DH = 64, DM = 1024;
constexpr int QL = 1024, ML = 1024, KL = 2048, BS = 4;

// ---------------- scratch (device globals; no allocation) ----------------
__device__ __half g_Ah [(size_t)8192 * 1024];   // fp16 cat rows (m = k2*4+b)
__device__ __half g_W3h[(size_t)3072 * 1024];   // fp16 qkv_w
__device__ __half g_Ph [(size_t)2048 * 1024];   // fp16 r input
__device__ __half g_Wrh[(size_t)1024 * 1024];   // fp16 r_net_w
__device__ __half g_Woh[(size_t)1024 * 1024];   // fp16 o_w
__device__ __half g_Qwh[(size_t)BS * NH * QL * DH];  // (q+rw_bias)*0.125  [b*16+n][i][d]
__device__ __half g_Kh [(size_t)BS * NH * KL * DH];  // [b*16+n][j][d]
__device__ __half g_Vt [(size_t)BS * NH * DH * KL];  // [b*16+n][d][j]  (transposed)
__device__ __half g_Rh [(size_t)NH * KL * DH];       // [n][rel][d]
__device__ __half g_Th [(size_t)64 * QL * KL];       // T2[z][i][j] = BD[i][j] (pre-shifted)
__device__ __half g_avh[(size_t)QL * BS * DM];       // attn_vec rows m = i*4+b
__device__ float  g_tmp[(size_t)QL * BS * DM];       // w + attn_out (pre-LN)
__device__ float  g_brr[NH * KL];                    // (rr-rw)*0.125 . R[n][rel]

// ---------------- PTX helpers ----------------
__device__ __forceinline__ uint32_t smem_u32(const void* p) {
    uint32_t a;
    asm("{ .reg .u64 t; cvta.to.shared.u64 t, %1; cvt.u32.u64 %0, t; }" : "=r"(a) : "l"(p));
    return a;
}
__device__ __forceinline__ void ldsm_x4(uint32_t& r0, uint32_t& r1, uint32_t& r2, uint32_t& r3,
                                        uint32_t addr) {
    asm volatile("ldmatrix.sync.aligned.m8n8.x4.shared.b16 {%0,%1,%2,%3}, [%4];"
                 : "=r"(r0), "=r"(r1), "=r"(r2), "=r"(r3) : "r"(addr));
}
__device__ __forceinline__ void mma16816(float* d, const uint32_t* a, const uint32_t* b) {
    asm volatile("mma.sync.aligned.m16n8k16.row.col.f32.f16.f16.f32 "
                 "{%0,%1,%2,%3}, {%4,%5,%6,%7}, {%8,%9}, {%0,%1,%2,%3};"
                 : "+f"(d[0]), "+f"(d[1]), "+f"(d[2]), "+f"(d[3])
                 : "r"(a[0]), "r"(a[1]), "r"(a[2]), "r"(a[3]), "r"(b[0]), "r"(b[1]));
}
__device__ __forceinline__ uint32_t pack_h2(float x, float y) {
    __half2 h = __floats2half2_rn(x, y);
    return *(uint32_t*)&h;
}
__device__ __forceinline__ void cp_async16(uint32_t saddr, const void* gptr) {
    asm volatile("cp.async.cg.shared.global [%0], [%1], 16;" :: "r"(saddr), "l"(gptr));
}
__device__ __forceinline__ void cp_commit() { asm volatile("cp.async.commit_group;"); }
__device__ __forceinline__ void cp_wait0()  { asm volatile("cp.async.wait_group 0;"); }
__device__ __forceinline__ void cp_wait1()  { asm volatile("cp.async.wait_group 1;"); }

// ============ fused fp32 -> fp16 conversion (all 6 tensors, one launch) ============
__global__ void __launch_bounds__(256) conv_all(const float* __restrict__ mems,
                                                const float* __restrict__ w,
                                                const float* __restrict__ qkv_w,
                                                const float* __restrict__ r,
                                                const float* __restrict__ r_net_w,
                                                const float* __restrict__ o_w) {
    const int bid = blockIdx.x;
    const float* src;
    __half* dst;
    int rel;
    if (bid < 4096)        { src = mems;    dst = g_Ah;                         rel = bid; }
    else if (bid < 8192)   { src = w;       dst = g_Ah + (size_t)4096 * 1024;   rel = bid - 4096; }
    else if (bid < 11264)  { src = qkv_w;   dst = g_W3h;                        rel = bid - 8192; }
    else if (bid < 13312)  { src = r;       dst = g_Ph;                         rel = bid - 11264; }
    else if (bid < 14336)  { src = r_net_w; dst = g_Wrh;                       rel = bid - 13312; }
    else                   { src = o_w;     dst = g_Woh;                       rel = bid - 14336; }
    const int i = rel * 256 + threadIdx.x;
    float4 v = ((const float4*)src)[i];
    __half2* d2 = (__half2*)dst;
    d2[2 * i]     = __floats2half2_rn(v.x, v.y);
    d2[2 * i + 1] = __floats2half2_rn(v.z, v.w);
}

// ============ warp-tiled HMMA GEMM, D = A @ B^T, 8 warps x (64x32) ============
// 3-stage cp.async pipeline, KCHUNK=16 (never fully drains in steady state)
// MODE 0: qkv   M=8192 N=3072 K=1024  -> scatter Qwh/Kh/Vt     (aux = rw_bias)
// MODE 1: r     M=2048 N=1024 K=1024  -> scatter Rh
// MODE 2: o     M=4096 N=1024 K=1024  -> g_tmp = D + aux(=w)
// MODE 3: T2    M=1024 N=2048 K=64    batched z=64, +brr, rel-shifted fp16 out
template <int MODE>
__global__ void __launch_bounds__(256) gemm_mma(const float* __restrict__ aux) {
    constexpr int K  = (MODE <= 2) ? 1024 : 64;
    constexpr int MT = 4, NT = 4;           // per-warp 64x32
    constexpr int LDS = 24;                 // 16 data + 8 pad halves (48B rows)
    constexpr int KC = K / 16;              // 64 or 4 chunks

    if constexpr (MODE == 3) {
        if (blockIdx.x + blockIdx.y < 7) return;   // dead T tiles (never read)
    }

    __shared__ __align__(16) __half As[3][128 * LDS];   // 3 x 6144 B
    __shared__ __align__(16) __half Bs[3][128 * LDS];   // total 36864 B

    const int t = threadIdx.x, lane = t & 31, wid = t >> 5;
    const int wy = wid & 1, wx = wid >> 1;           // 2 x 4 warps -> (64, 32) tiles
    const int bm = blockIdx.y * 128, bn = blockIdx.x * 128;
    const int z = blockIdx.z;

    const __half* Ab;
    const __half* Bb;
    if constexpr (MODE == 0)      { Ab = g_Ah;  Bb = g_W3h; }
    else if constexpr (MODE == 1) { Ab = g_Ph;  Bb = g_Wrh; }
    else if constexpr (MODE == 2) { Ab = g_avh; Bb = g_Woh; }
    else { Ab = g_Qwh + (size_t)z * QL * DH; Bb = g_Rh + (size_t)(z & 15) * KL * DH; }

    // loader: 256 threads cover 128 rows x 2 x 16B chunks per operand (1 uint4 each)
    const int lrow = t >> 1, lc = (t & 1) * 8;
    const __half* aGp = Ab + (size_t)(bm + lrow) * K + lc;
    const __half* bGp = Bb + (size_t)(bn + lrow) * K + lc;
    const uint32_t sOff = (uint32_t)(lrow * LDS + lc) * 2;
    uint32_t sA[3], sB[3];
#pragma unroll
    for (int s = 0; s < 3; s++) {
        sA[s] = smem_u32(&As[s][0]);
        sB[s] = smem_u32(&Bs[s][0]);
    }

    // prologue: prefetch chunks 0,1 into buffers 0,1
    cp_async16(sA[0] + sOff, aGp);
    cp_async16(sB[0] + sOff, bGp);
    cp_commit();
    if (KC > 1) {
        cp_async16(sA[1] + sOff, aGp + 16);
        cp_async16(sB[1] + sOff, bGp + 16);
        cp_commit();
    }

    float D[MT][NT][4];
#pragma unroll
    for (int mt = 0; mt < MT; mt++)
#pragma unroll
        for (int nt = 0; nt < NT; nt++)
#pragma unroll
            for (int r = 0; r < 4; r++) D[mt][nt][r] = 0.f;

    // per-thread ldsm addresses (relative, buffer base added per chunk)
    const uint32_t aOff = 2 * ((wy * 64 + (lane & 15)) * LDS + (lane >> 4) * 8);
    const uint32_t bOff = 2 * ((wx * 32 + (lane & 7) + ((lane >> 4) << 3)) * LDS
                               + ((lane >> 3) & 1) * 8);

    for (int kc = 0; kc < KC; kc++) {
        if (kc + 1 < KC) cp_wait1(); else cp_wait0();   // chunk kc landed
        __syncthreads();                                 // all warps past compute kc-1
        if (kc + 2 < KC) {                               // prefetch into freed buffer
            const int nb = (kc + 2) % 3;
            cp_async16(sA[nb] + sOff, aGp + (kc + 2) * 16);
            cp_async16(sB[nb] + sOff, bGp + (kc + 2) * 16);
            cp_commit();
        }
        const int cur = kc % 3;
        uint32_t af[MT][4], bf[NT][2];
#pragma unroll
        for (int mt = 0; mt < MT; mt++)
            ldsm_x4(af[mt][0], af[mt][1], af[mt][2], af[mt][3],
                    sA[cur] + aOff + (uint32_t)(2 * mt * 16 * LDS));
#pragma unroll
        for (int np = 0; np < NT / 2; np++)
            ldsm_x4(bf[2 * np][0], bf[2 * np][1], bf[2 * np + 1][0], bf[2 * np + 1][1],
                    sB[cur] + bOff + (uint32_t)(2 * np * 16 * LDS));
#pragma unroll
        for (int mt = 0; mt < MT; mt++)
#pragma unroll
            for (int nt = 0; nt < NT; nt++)
                mma16816(D[mt][nt], af[mt], bf[nt]);
    }

    // ---------------- epilogue ----------------
#pragma unroll
    for (int mt = 0; mt < MT; mt++) {
#pragma unroll
        for (int nt = 0; nt < NT; nt++) {
#pragma unroll
            for (int r = 0; r < 4; r++) {
                const int row = bm + wy * 64 + mt * 16 + (lane >> 2) + ((r >> 1) << 3);
                const int col = bn + wx * 32 + nt * 8 + ((lane & 3) << 1) + (r & 1);
                const float v = D[mt][nt][r];
                if constexpr (MODE == 0) {
                    const int k2 = row >> 2, b = row & 3;
                    const int region = col >> 10, oo = col & 1023;
                    const int n = oo >> 6, d = oo & 63;
                    if (region == 0) {
                        if (k2 >= ML)
                            g_Qwh[(((size_t)(b * NH + n)) * QL + (k2 - ML)) * DH + d] =
                                __float2half((v + aux[oo]) * 0.125f);
                    } else if (region == 1) {
                        g_Kh[(((size_t)(b * NH + n)) * KL + k2) * DH + d] = __float2half(v);
                    } else {
                        g_Vt[(((size_t)(b * NH + n)) * DH + d) * KL + k2] = __float2half(v);
                    }
                } else if constexpr (MODE == 1) {
                    g_Rh[(((size_t)(col >> 6)) * KL + row) * DH + (col & 63)] = __float2half(v);
                } else if constexpr (MODE == 2) {
                    g_tmp[(size_t)row * DM + col] = v + aux[(size_t)row * DM + col];
                } else {
                    // pre-shifted store: T2[row][j] with j = rel + row - 1023
                    const int j = col + row - 1023;
                    if (j >= 0)
                        g_Th[((size_t)z * QL + row) * KL + j] =
                            __float2half(v + g_brr[(z & 15) * KL + col]);
                }
            }
        }
    }
}

// ============ brr[n][rel] = ((rr-rw)*0.125) . R[n][rel] ============
__global__ void __launch_bounds__(256) brr_kernel(const float* __restrict__ rr_bias,
                                                  const float* __restrict__ rw_bias) {
    int idx = blockIdx.x * 256 + threadIdx.x;
    int n = idx >> 11, rel = idx & (KL - 1);
    const __half* Rp = g_Rh + ((size_t)n * KL + rel) * DH;
    float acc = 0.f;
#pragma unroll
    for (int c = 0; c < DH; c++)
        acc = fmaf((rr_bias[n * DH + c] - rw_bias[n * DH + c]) * 0.125f,
                   __half2float(Rp[c]), acc);
    g_brr[idx] = acc;
}

// ============ flash attention, TJ=64, cp.async double-buffered K/V ============
constexpr int FSTR = 72;   // row stride (64 data + 8 pad)

__global__ void __launch_bounds__(256, 2) flash_kernel() {
    __shared__ __align__(16) __half Ks[2][64 * FSTR];   // 18432 B (Q staging uses both)
    __shared__ __align__(16) __half Vs[2][64 * FSTR];   // 18432 B  (total 36864 B)

    const int t = threadIdx.x, lane = t & 31, wid = t >> 5;
    const int ib = gridDim.x - 1 - blockIdx.x;        // heavy blocks first
    const int i0 = ib * 128, z = blockIdx.y;
    const int b = z >> 4, n = z & 15;

    const __half* Qb = g_Qwh + (size_t)z * QL * DH;
    const __half* Kb = g_Kh + (size_t)z * KL * DH;
    const __half* Vb = g_Vt + (size_t)z * DH * KL;
    const __half* Tb = g_Th + (size_t)z * QL * KL;

    // Q staging across both K buffers (contiguous 128 rows), extract A-frags
    __half* Qs = &Ks[0][0];
#pragma unroll
    for (int u = 0; u < 4; u++) {
        int idx = t + u * 256;
        int row = idx >> 3, c = (idx & 7) * 8;
        *(uint4*)&Qs[row * FSTR + c] = *(const uint4*)(Qb + (size_t)(i0 + row) * DH + c);
    }
    __syncthreads();
    uint32_t qf[4][4];
    {
        uint32_t smA = smem_u32(Qs);
#pragma unroll
        for (int ks = 0; ks < 4; ks++) {
            uint32_t a = smA + 2 * ((wid * 16 + (lane & 15)) * FSTR + ks * 16 + (lane >> 4) * 8);
            ldsm_x4(qf[ks][0], qf[ks][1], qf[ks][2], qf[ks][3], a);
        }
    }
    __syncthreads();   // all warps done reading Q before K prefetch overwrites

    const uint32_t sK[2] = {smem_u32(&Ks[0][0]), smem_u32(&Ks[1][0])};
    const uint32_t sV[2] = {smem_u32(&Vs[0][0]), smem_u32(&Vs[1][0])};
    // per-thread load slots: 2 uint4 each for K and V per tile
    const int lrow = t >> 3, lc = (t & 7) * 8;          // rows 0..31 (u=0) / 32..63 (u=1)
    const uint32_t lOff0 = (uint32_t)(lrow * FSTR + lc) * 2;
    const uint32_t lOff1 = (uint32_t)((lrow + 32) * FSTR + lc) * 2;

    const int njt = ib * 2 + 18;                        // 64-wide tiles

    // prefetch tile 0 -> buffer 0
    {
        cp_async16(sK[0] + lOff0, Kb + (size_t)lrow * DH + lc);
        cp_async16(sK[0] + lOff1, Kb + (size_t)(lrow + 32) * DH + lc);
        cp_async16(sV[0] + lOff0, Vb + (size_t)lrow * KL + lc);
        cp_async16(sV[0] + lOff1, Vb + (size_t)(lrow + 32) * KL + lc);
        cp_commit();
    }

    float O[8][4];
#pragma unroll
    for (int i = 0; i < 8; i++)
#pragma unroll
        for (int r = 0; r < 4; r++) O[i][r] = 0.f;
    float m0 = -1e30f, m1 = -1e30f, l0 = 0.f, l1 = 0.f;

    const int rbase = i0 + wid * 16 + (lane >> 2);    // row of d0/d1; d2/d3 at rbase+8
    const int ccb = (lane & 3) * 2;
    const __half* Tr0 = Tb + (size_t)rbase * KL + ccb;
    const __half* Tr1 = Tb + (size_t)(rbase + 8) * KL + ccb;

    for (int jt = 0; jt < njt; jt++) {
        const int j0 = jt * 64;
        const int cur = jt & 1;
        const bool pf = (jt + 1 < njt);
        if (pf) {
            const int nb = 1 - cur;
            const int jn = j0 + 64;
            cp_async16(sK[nb] + lOff0, Kb + (size_t)(jn + lrow) * DH + lc);
            cp_async16(sK[nb] + lOff1, Kb + (size_t)(jn + lrow + 32) * DH + lc);
            cp_async16(sV[nb] + lOff0, Vb + (size_t)lrow * KL + jn + lc);
            cp_async16(sV[nb] + lOff1, Vb + (size_t)(lrow + 32) * KL + jn + lc);
            cp_commit();
            cp_wait1();
        } else {
            cp_wait0();
        }
        __syncthreads();

        float S[8][4];
#pragma unroll
        for (int nt = 0; nt < 8; nt++)
#pragma unroll
            for (int r = 0; r < 4; r++) S[nt][r] = 0.f;

        const uint32_t smB = sK[cur];
#pragma unroll
        for (int ks = 0; ks < 4; ks++) {
            uint32_t bf[4][4];
#pragma unroll
            for (int np = 0; np < 4; np++) {
                uint32_t a = smB + 2 * ((np * 16 + (lane & 7) + ((lane >> 4) << 3)) * FSTR
                                        + ks * 16 + ((lane >> 3) & 1) * 8);
                ldsm_x4(bf[np][0], bf[np][1], bf[np][2], bf[np][3], a);
            }
#pragma unroll
            for (int nt = 0; nt < 8; nt++) {
                uint32_t bb[2] = {bf[nt >> 1][(nt & 1) * 2], bf[nt >> 1][(nt & 1) * 2 + 1]};
                mma16816(S[nt], qf[ks], bb);
            }
        }

        // add T2 (contains brr, pre-shifted => contiguous aligned half2); causal mask
        const bool partial = (j0 + 63 > i0 + ML);
        if (!partial) {
#pragma unroll
            for (int nt = 0; nt < 8; nt++) {
                __half2 a0 = *(const __half2*)(Tr0 + j0 + nt * 8);
                __half2 a1 = *(const __half2*)(Tr1 + j0 + nt * 8);
                S[nt][0] += __low2float(a0);  S[nt][1] += __high2float(a0);
                S[nt][2] += __low2float(a1);  S[nt][3] += __high2float(a1);
            }
        } else {
#pragma unroll
            for (int nt = 0; nt < 8; nt++) {
                __half2 a0 = *(const __half2*)(Tr0 + j0 + nt * 8);
                __half2 a1 = *(const __half2*)(Tr1 + j0 + nt * 8);
                const int c0 = j0 + ccb + nt * 8;
                S[nt][0] = (c0     <= rbase + ML)     ? S[nt][0] + __low2float(a0)  : -1e30f;
                S[nt][1] = (c0 + 1 <= rbase + ML)     ? S[nt][1] + __high2float(a0) : -1e30f;
                S[nt][2] = (c0     <= rbase + 8 + ML) ? S[nt][2] + __low2float(a1)  : -1e30f;
                S[nt][3] = (c0 + 1 <= rbase + 8 + ML) ? S[nt][3] + __high2float(a1) : -1e30f;
            }
        }

        // online softmax
        float mx0 = -1e30f, mx1 = -1e30f;
#pragma unroll
        for (int nt = 0; nt < 8; nt++) {
            mx0 = fmaxf(mx0, fmaxf(S[nt][0], S[nt][1]));
            mx1 = fmaxf(mx1, fmaxf(S[nt][2], S[nt][3]));
        }
        mx0 = fmaxf(mx0, __shfl_xor_sync(0xffffffffu, mx0, 1));
        mx0 = fmaxf(mx0, __shfl_xor_sync(0xffffffffu, mx0, 2));
        mx1 = fmaxf(mx1, __shfl_xor_sync(0xffffffffu, mx1, 1));
        mx1 = fmaxf(mx1, __shfl_xor_sync(0xffffffffu, mx1, 2));
        const float mn0 = fmaxf(m0, mx0), mn1 = fmaxf(m1, mx1);
        const float cr0 = __expf(m0 - mn0), cr1 = __expf(m1 - mn1);
        l0 *= cr0; l1 *= cr1;
#pragma unroll
        for (int i = 0; i < 8; i++) {
            O[i][0] *= cr0; O[i][1] *= cr0; O[i][2] *= cr1; O[i][3] *= cr1;
        }
#pragma unroll
        for (int nt = 0; nt < 8; nt++) {
            S[nt][0] = __expf(S[nt][0] - mn0);
            S[nt][1] = __expf(S[nt][1] - mn0);
            S[nt][2] = __expf(S[nt][2] - mn1);
            S[nt][3] = __expf(S[nt][3] - mn1);
            l0 += S[nt][0] + S[nt][1];
            l1 += S[nt][2] + S[nt][3];
        }
        m0 = mn0; m1 = mn1;

        // P @ V  (A-frags repacked from S registers; V B-frags from smem)
        const uint32_t smV = sV[cur];
#pragma unroll
        for (int kp = 0; kp < 4; kp++) {
            uint32_t af[4];
            af[0] = pack_h2(S[2 * kp][0],     S[2 * kp][1]);
            af[1] = pack_h2(S[2 * kp][2],     S[2 * kp][3]);
            af[2] = pack_h2(S[2 * kp + 1][0], S[2 * kp + 1][1]);
            af[3] = pack_h2(S[2 * kp + 1][2], S[2 * kp + 1][3]);
            uint32_t vf[4][4];
#pragma unroll
            for (int np = 0; np < 4; np++) {
                uint32_t a = smV + 2 * ((np * 16 + (lane & 7) + ((lane >> 4) << 3)) * FSTR
                                        + kp * 16 + ((lane >> 3) & 1) * 8);
                ldsm_x4(vf[np][0], vf[np][1], vf[np][2], vf[np][3], a);
            }
#pragma unroll
            for (int nt2 = 0; nt2 < 8; nt2++) {
                uint32_t bb[2] = {vf[nt2 >> 1][(nt2 & 1) * 2], vf[nt2 >> 1][(nt2 & 1) * 2 + 1]};
                mma16816(O[nt2], af, bb);
            }
        }
        __syncthreads();   // compute done before next iteration overwrites old buffer
    }

    // finalize: reduce l over the 4 lanes sharing each row, scale, store fp16
    l0 += __shfl_xor_sync(0xffffffffu, l0, 1);
    l0 += __shfl_xor_sync(0xffffffffu, l0, 2);
    l1 += __shfl_xor_sync(0xffffffffu, l1, 1);
    l1 += __shfl_xor_sync(0xffffffffu, l1, 2);
    const float inv0 = 1.f / l0, inv1 = 1.f / l1;
    __half2* W0 = (__half2*)(g_avh + ((size_t)rbase * BS + b) * DM + n * DH);
    __half2* W1 = (__half2*)(g_avh + ((size_t)(rbase + 8) * BS + b) * DM + n * DH);
    const int cd = lane & 3;
#pragma unroll
    for (int nt2 = 0; nt2 < 8; nt2++) {
        W0[nt2 * 4 + cd] = __floats2half2_rn(O[nt2][0] * inv0, O[nt2][1] * inv0);
        W1[nt2 * 4 + cd] = __floats2half2_rn(O[nt2][2] * inv1, O[nt2][3] * inv1);
    }
}

// ============ LayerNorm ============
__global__ void __launch_bounds__(256) ln_kernel(const float* __restrict__ gamma,
                                                 const float* __restrict__ beta,
                                                 float* __restrict__ out) {
    const int row = blockIdx.x;
    const float* x = g_tmp + (size_t)row * DM;
    float s = 0.f, ss = 0.f;
#pragma unroll
    for (int u = 0; u < 4; u++) {
        float v = x[threadIdx.x + u * 256];
        s += v; ss += v * v;
    }
#pragma unroll
    for (int off = 16; off; off >>= 1) {
        s += __shfl_xor_sync(0xffffffffu, s, off);
        ss += __shfl_xor_sync(0xffffffffu, ss, off);
    }
    __shared__ float sm_s[8], sm_ss[8];
    int wid = threadIdx.x >> 5, lid = threadIdx.x & 31;
    if (lid == 0) { sm_s[wid] = s; sm_ss[wid] = ss; }
    __syncthreads();
    if (threadIdx.x == 0) {
        float a = 0.f, b2 = 0.f;
#pragma unroll
        for (int i2 = 0; i2 < 8; i2++) { a += sm_s[i2]; b2 += sm_ss[i2]; }
        sm_s[0] = a; sm_ss[0] = b2;
    }
    __syncthreads();
    const float mu = sm_s[0] * (1.f / DM);
    const float var = sm_ss[0] * (1.f / DM) - mu * mu;
    const float inv = rsqrtf(var + 1e-5f);
#pragma unroll
    for (int u = 0; u < 4; u++) {
        int c = threadIdx.x + u * 256;
        out[(size_t)row * DM + c] = (x[c] - mu) * inv * gamma[c] + beta[c];
    }
}

// ============ launch ============
extern "C" void kernel_launch(void* const* d_in, const int* in_sizes, int n_in,
                              void* d_out, int out_size) {
    const float* w       = (const float*)d_in[0];   // [1024,4,1024]
    const float* r       = (const float*)d_in[1];   // [2048,1024]
    const float* mems    = (const float*)d_in[2];   // [1024,4,1024]
    // d_in[3] = attn_mask (unused; mask computed analytically: j > i + MLEN)
    const float* qkv_w   = (const float*)d_in[4];   // [3072,1024]
    const float* r_net_w = (const float*)d_in[5];   // [1024,1024]
    const float* o_w     = (const float*)d_in[6];   // [1024,1024]
    const float* rr_bias = (const float*)d_in[7];   // [16,64]
    const float* rw_bias = (const float*)d_in[8];   // [16,64]
    const float* ln_g    = (const float*)d_in[9];   // [1024]
    const float* ln_b    = (const float*)d_in[10];  // [1024]
    float* out = (float*)d_out;

    // round-15 structure; only gemm_mma internals changed (3-stage pipeline)
    conv_all<<<15360, 256>>>(mems, w, qkv_w, r, r_net_w, o_w);   // (1) all fp32->fp16
    gemm_mma<1><<<dim3(8, 16), 256>>>(nullptr);                  // (2) R proj
    brr_kernel<<<NH * KL / 256, 256>>>(rr_bias, rw_bias);        // (3) brr
    gemm_mma<0><<<dim3(24, 64), 256>>>(rw_bias);                 // (4) QKV proj  [profiled]
    gemm_mma<3><<<dim3(16, 8, 64), 256>>>(nullptr);              // (5) T2 = shift(Qw@R^T+brr)
    flash_kernel<<<dim3(8, 64), 256>>>();                        // (6) fused S/softmax/PV
    gemm_mma<2><<<dim3(8, 32), 256>>>(w);                        // (7) O proj + residual
    ln_kernel<<<4096, 256>>>(ln_g, ln_b, out);                   // (8) LayerNorm
}

// round 17
// speedup vs baseline: 1.1151x; 1.1151x over previous
#include <cuda_runtime.h>
#include <cuda_fp16.h>
#include <math.h>
#include <cstdint>

// ---------------- problem constants ----------------
constexpr int NH = 16, DH = 64, DM = 1024;
constexpr int QL = 1024, ML = 1024, KL = 2048, BS = 4;

// ---------------- scratch (device globals; no allocation) ----------------
__device__ __half g_Ah [(size_t)8192 * 1024];   // fp16 cat rows (m = k2*4+b)
__device__ __half g_W3h[(size_t)3072 * 1024];   // fp16 qkv_w
__device__ __half g_Ph [(size_t)2048 * 1024];   // fp16 r input
__device__ __half g_Wrh[(size_t)1024 * 1024];   // fp16 r_net_w
__device__ __half g_Woh[(size_t)1024 * 1024];   // fp16 o_w
__device__ __half g_Qwh[(size_t)BS * NH * QL * DH];  // (q+rw_bias)*0.125  [b*16+n][i][d]
__device__ __half g_Kh [(size_t)BS * NH * KL * DH];  // [b*16+n][j][d]
__device__ __half g_Vt [(size_t)BS * NH * DH * KL];  // [b*16+n][d][j]  (transposed)
__device__ __half g_Rh [(size_t)NH * KL * DH];       // [n][rel][d]
__device__ __half g_Th [(size_t)64 * QL * KL];       // T2[z][i][j] = BD[i][j] (pre-shifted)
__device__ __half g_avh[(size_t)QL * BS * DM];       // attn_vec rows m = i*4+b
__device__ float  g_tmp[(size_t)QL * BS * DM];       // w + attn_out (pre-LN)
__device__ float  g_brr[NH * KL];                    // (rr-rw)*0.125 . R[n][rel]

// ---------------- PTX helpers ----------------
__device__ __forceinline__ uint32_t smem_u32(const void* p) {
    uint32_t a;
    asm("{ .reg .u64 t; cvta.to.shared.u64 t, %1; cvt.u32.u64 %0, t; }" : "=r"(a) : "l"(p));
    return a;
}
__device__ __forceinline__ void ldsm_x4(uint32_t& r0, uint32_t& r1, uint32_t& r2, uint32_t& r3,
                                        uint32_t addr) {
    asm volatile("ldmatrix.sync.aligned.m8n8.x4.shared.b16 {%0,%1,%2,%3}, [%4];"
                 : "=r"(r0), "=r"(r1), "=r"(r2), "=r"(r3) : "r"(addr));
}
__device__ __forceinline__ void mma16816(float* d, const uint32_t* a, const uint32_t* b) {
    asm volatile("mma.sync.aligned.m16n8k16.row.col.f32.f16.f16.f32 "
                 "{%0,%1,%2,%3}, {%4,%5,%6,%7}, {%8,%9}, {%0,%1,%2,%3};"
                 : "+f"(d[0]), "+f"(d[1]), "+f"(d[2]), "+f"(d[3])
                 : "r"(a[0]), "r"(a[1]), "r"(a[2]), "r"(a[3]), "r"(b[0]), "r"(b[1]));
}
__device__ __forceinline__ uint32_t pack_h2(float x, float y) {
    __half2 h = __floats2half2_rn(x, y);
    return *(uint32_t*)&h;
}
__device__ __forceinline__ void cp_async16(uint32_t saddr, const void* gptr) {
    asm volatile("cp.async.cg.shared.global [%0], [%1], 16;" :: "r"(saddr), "l"(gptr));
}
__device__ __forceinline__ void cp_commit() { asm volatile("cp.async.commit_group;"); }
__device__ __forceinline__ void cp_wait0()  { asm volatile("cp.async.wait_group 0;"); }
__device__ __forceinline__ void cp_wait1()  { asm volatile("cp.async.wait_group 1;"); }

// ============ fused fp32 -> fp16 conversion (all 6 tensors, one launch) ============
__global__ void __launch_bounds__(256) conv_all(const float* __restrict__ mems,
                                                const float* __restrict__ w,
                                                const float* __restrict__ qkv_w,
                                                const float* __restrict__ r,
                                                const float* __restrict__ r_net_w,
                                                const float* __restrict__ o_w) {
    const int bid = blockIdx.x;
    const float* src;
    __half* dst;
    int rel;
    if (bid < 4096)        { src = mems;    dst = g_Ah;                         rel = bid; }
    else if (bid < 8192)   { src = w;       dst = g_Ah + (size_t)4096 * 1024;   rel = bid - 4096; }
    else if (bid < 11264)  { src = qkv_w;   dst = g_W3h;                        rel = bid - 8192; }
    else if (bid < 13312)  { src = r;       dst = g_Ph;                         rel = bid - 11264; }
    else if (bid < 14336)  { src = r_net_w; dst = g_Wrh;                       rel = bid - 13312; }
    else                   { src = o_w;     dst = g_Woh;                       rel = bid - 14336; }
    const int i = rel * 256 + threadIdx.x;
    float4 v = ((const float4*)src)[i];
    __half2* d2 = (__half2*)dst;
    d2[2 * i]     = __floats2half2_rn(v.x, v.y);
    d2[2 * i + 1] = __floats2half2_rn(v.z, v.w);
}

// ============ warp-tiled HMMA GEMM, D = A @ B^T, 8 warps x (64x32), cp.async ============
// MODE 0: qkv   M=8192 N=3072 K=1024  -> scatter Qwh/Kh/Vt     (aux = rw_bias)
// MODE 1: r     M=2048 N=1024 K=1024  -> scatter Rh
// MODE 2: o     M=4096 N=1024 K=1024  -> g_tmp = D + aux(=w)
// MODE 3: T2    M=1024 N=2048 K=64    batched z=64, +brr, rel-shifted fp16 out
template <int MODE>
__global__ void __launch_bounds__(256) gemm_mma(const float* __restrict__ aux) {
    constexpr int K  = (MODE <= 2) ? 1024 : 64;
    constexpr int MT = 4, NT = 4;           // per-warp 64x32
    constexpr int LDS = 40;
    constexpr int KC = K / 32;

    if constexpr (MODE == 3) {
        if (blockIdx.x + blockIdx.y < 7) return;   // dead T tiles (never read)
    }
    if constexpr (MODE == 0) {
        // Q region (cols < 1024) only kept for rows >= 4096 (k2 >= ML):
        // tiles with bx<8 && by<32 are computed then fully discarded -> skip.
        if (blockIdx.x < 8 && blockIdx.y < 32) return;
    }

    __shared__ __align__(16) __half As[2][128 * LDS];
    __shared__ __align__(16) __half Bs[2][128 * LDS];

    const int t = threadIdx.x, lane = t & 31, wid = t >> 5;
    const int wy = wid & 1, wx = wid >> 1;           // 2 x 4 warps -> (64, 32) tiles
    const int bm = blockIdx.y * 128, bn = blockIdx.x * 128;
    const int z = blockIdx.z;

    const __half* Ab;
    const __half* Bb;
    if constexpr (MODE == 0)      { Ab = g_Ah;  Bb = g_W3h; }
    else if constexpr (MODE == 1) { Ab = g_Ph;  Bb = g_Wrh; }
    else if constexpr (MODE == 2) { Ab = g_avh; Bb = g_Woh; }
    else { Ab = g_Qwh + (size_t)z * QL * DH; Bb = g_Rh + (size_t)(z & 15) * KL * DH; }

    // loader: 256 threads x 2 iters cover 128 rows x 4 x 16B chunks (per operand)
    const __half* aG[2];
    const __half* bG[2];
    uint32_t sOff[2];
    const uint32_t sA0 = smem_u32(&As[0][0]), sA1 = smem_u32(&As[1][0]);
    const uint32_t sB0 = smem_u32(&Bs[0][0]), sB1 = smem_u32(&Bs[1][0]);
#pragma unroll
    for (int u = 0; u < 2; u++) {
        int g = t + u * 256;
        int row = g >> 2, c4 = (g & 3) * 8;
        aG[u] = Ab + (size_t)(bm + row) * K + c4;
        bG[u] = Bb + (size_t)(bn + row) * K + c4;
        sOff[u] = (uint32_t)(row * LDS + c4) * 2;
    }

    // preload chunk 0 -> buffer 0
#pragma unroll
    for (int u = 0; u < 2; u++) {
        cp_async16(sA0 + sOff[u], aG[u]);
        cp_async16(sB0 + sOff[u], bG[u]);
    }
    cp_commit();
    cp_wait0();
    __syncthreads();

    float D[MT][NT][4];
#pragma unroll
    for (int mt = 0; mt < MT; mt++)
#pragma unroll
        for (int nt = 0; nt < NT; nt++)
#pragma unroll
            for (int r = 0; r < 4; r++) D[mt][nt][r] = 0.f;

    for (int kc = 0; kc < KC; kc++) {
        const int cur = kc & 1;
        const bool pf = (kc + 1 < KC);
        if (pf) {
            const uint32_t dA = cur ? sA0 : sA1;
            const uint32_t dB = cur ? sB0 : sB1;
#pragma unroll
            for (int u = 0; u < 2; u++) {
                cp_async16(dA + sOff[u], aG[u] + (kc + 1) * 32);
                cp_async16(dB + sOff[u], bG[u] + (kc + 1) * 32);
            }
            cp_commit();
        }
        const uint32_t smA = cur ? sA1 : sA0;
        const uint32_t smB = cur ? sB1 : sB0;
#pragma unroll
        for (int ks = 0; ks < 2; ks++) {
            uint32_t af[MT][4], bf[NT][2];
#pragma unroll
            for (int mt = 0; mt < MT; mt++) {
                uint32_t a = smA + 2 * ((wy * 64 + mt * 16 + (lane & 15)) * LDS
                                        + ks * 16 + (lane >> 4) * 8);
                ldsm_x4(af[mt][0], af[mt][1], af[mt][2], af[mt][3], a);
            }
#pragma unroll
            for (int np = 0; np < NT / 2; np++) {
                uint32_t a = smB + 2 * ((wx * 32 + np * 16 + (lane & 7) + ((lane >> 4) << 3)) * LDS
                                        + ks * 16 + ((lane >> 3) & 1) * 8);
                ldsm_x4(bf[2 * np][0], bf[2 * np][1], bf[2 * np + 1][0], bf[2 * np + 1][1], a);
            }
#pragma unroll
            for (int mt = 0; mt < MT; mt++)
#pragma unroll
                for (int nt = 0; nt < NT; nt++)
                    mma16816(D[mt][nt], af[mt], bf[nt]);
        }
        if (pf) {
            cp_wait0();
            __syncthreads();
        }
    }

    // ---------------- epilogue ----------------
#pragma unroll
    for (int mt = 0; mt < MT; mt++) {
#pragma unroll
        for (int nt = 0; nt < NT; nt++) {
#pragma unroll
            for (int r = 0; r < 4; r++) {
                const int row = bm + wy * 64 + mt * 16 + (lane >> 2) + ((r >> 1) << 3);
                const int col = bn + wx * 32 + nt * 8 + ((lane & 3) << 1) + (r & 1);
                const float v = D[mt][nt][r];
                if constexpr (MODE == 0) {
                    const int k2 = row >> 2, b = row & 3;
                    const int region = col >> 10, oo = col & 1023;
                    const int n = oo >> 6, d = oo & 63;
                    if (region == 0) {
                        if (k2 >= ML)
                            g_Qwh[(((size_t)(b * NH + n)) * QL + (k2 - ML)) * DH + d] =
                                __float2half((v + aux[oo]) * 0.125f);
                    } else if (region == 1) {
                        g_Kh[(((size_t)(b * NH + n)) * KL + k2) * DH + d] = __float2half(v);
                    } else {
                        g_Vt[(((size_t)(b * NH + n)) * DH + d) * KL + k2] = __float2half(v);
                    }
                } else if constexpr (MODE == 1) {
                    g_Rh[(((size_t)(col >> 6)) * KL + row) * DH + (col & 63)] = __float2half(v);
                } else if constexpr (MODE == 2) {
                    g_tmp[(size_t)row * DM + col] = v + aux[(size_t)row * DM + col];
                } else {
                    // pre-shifted store: T2[row][j] with j = rel + row - 1023
                    const int j = col + row - 1023;
                    if (j >= 0)
                        g_Th[((size_t)z * QL + row) * KL + j] =
                            __float2half(v + g_brr[(z & 15) * KL + col]);
                }
            }
        }
    }
}

// ============ brr[n][rel] = ((rr-rw)*0.125) . R[n][rel] ============
__global__ void __launch_bounds__(256) brr_kernel(const float* __restrict__ rr_bias,
                                                  const float* __restrict__ rw_bias) {
    int idx = blockIdx.x * 256 + threadIdx.x;
    int n = idx >> 11, rel = idx & (KL - 1);
    const __half* Rp = g_Rh + ((size_t)n * KL + rel) * DH;
    float acc = 0.f;
#pragma unroll
    for (int c = 0; c < DH; c++)
        acc = fmaf((rr_bias[n * DH + c] - rw_bias[n * DH + c]) * 0.125f,
                   __half2float(Rp[c]), acc);
    g_brr[idx] = acc;
}

// ============ flash attention, TJ=64, cp.async double-buffered K/V ============
constexpr int FSTR = 72;   // row stride (64 data + 8 pad)

__global__ void __launch_bounds__(256, 2) flash_kernel() {
    __shared__ __align__(16) __half Ks[2][64 * FSTR];   // 18432 B (Q staging uses both)
    __shared__ __align__(16) __half Vs[2][64 * FSTR];   // 18432 B  (total 36864 B)

    const int t = threadIdx.x, lane = t & 31, wid = t >> 5;
    const int ib = gridDim.x - 1 - blockIdx.x;        // heavy blocks first
    const int i0 = ib * 128, z = blockIdx.y;
    const int b = z >> 4, n = z & 15;

    const __half* Qb = g_Qwh + (size_t)z * QL * DH;
    const __half* Kb = g_Kh + (size_t)z * KL * DH;
    const __half* Vb = g_Vt + (size_t)z * DH * KL;
    const __half* Tb = g_Th + (size_t)z * QL * KL;

    // Q staging across both K buffers (contiguous 128 rows), extract A-frags
    __half* Qs = &Ks[0][0];
#pragma unroll
    for (int u = 0; u < 4; u++) {
        int idx = t + u * 256;
        int row = idx >> 3, c = (idx & 7) * 8;
        *(uint4*)&Qs[row * FSTR + c] = *(const uint4*)(Qb + (size_t)(i0 + row) * DH + c);
    }
    __syncthreads();
    uint32_t qf[4][4];
    {
        uint32_t smA = smem_u32(Qs);
#pragma unroll
        for (int ks = 0; ks < 4; ks++) {
            uint32_t a = smA + 2 * ((wid * 16 + (lane & 15)) * FSTR + ks * 16 + (lane >> 4) * 8);
            ldsm_x4(qf[ks][0], qf[ks][1], qf[ks][2], qf[ks][3], a);
        }
    }
    __syncthreads();   // all warps done reading Q before K prefetch overwrites

    const uint32_t sK[2] = {smem_u32(&Ks[0][0]), smem_u32(&Ks[1][0])};
    const uint32_t sV[2] = {smem_u32(&Vs[0][0]), smem_u32(&Vs[1][0])};
    // per-thread load slots: 2 uint4 each for K and V per tile
    const int lrow = t >> 3, lc = (t & 7) * 8;          // rows 0..31 (u=0) / 32..63 (u=1)
    const uint32_t lOff0 = (uint32_t)(lrow * FSTR + lc) * 2;
    const uint32_t lOff1 = (uint32_t)((lrow + 32) * FSTR + lc) * 2;

    const int njt = ib * 2 + 18;                        // 64-wide tiles

    // prefetch tile 0 -> buffer 0
    {
        cp_async16(sK[0] + lOff0, Kb + (size_t)lrow * DH + lc);
        cp_async16(sK[0] + lOff1, Kb + (size_t)(lrow + 32) * DH + lc);
        cp_async16(sV[0] + lOff0, Vb + (size_t)lrow * KL + lc);
        cp_async16(sV[0] + lOff1, Vb + (size_t)(lrow + 32) * KL + lc);
        cp_commit();
    }

    float O[8][4];
#pragma unroll
    for (int i = 0; i < 8; i++)
#pragma unroll
        for (int r = 0; r < 4; r++) O[i][r] = 0.f;
    float m0 = -1e30f, m1 = -1e30f, l0 = 0.f, l1 = 0.f;

    const int rbase = i0 + wid * 16 + (lane >> 2);    // row of d0/d1; d2/d3 at rbase+8
    const int ccb = (lane & 3) * 2;
    const __half* Tr0 = Tb + (size_t)rbase * KL + ccb;
    const __half* Tr1 = Tb + (size_t)(rbase + 8) * KL + ccb;

    for (int jt = 0; jt < njt; jt++) {
        const int j0 = jt * 64;
        const int cur = jt & 1;
        const bool pf = (jt + 1 < njt);
        if (pf) {
            const int nb = 1 - cur;
            const int jn = j0 + 64;
            cp_async16(sK[nb] + lOff0, Kb + (size_t)(jn + lrow) * DH + lc);
            cp_async16(sK[nb] + lOff1, Kb + (size_t)(jn + lrow + 32) * DH + lc);
            cp_async16(sV[nb] + lOff0, Vb + (size_t)lrow * KL + jn + lc);
            cp_async16(sV[nb] + lOff1, Vb + (size_t)(lrow + 32) * KL + jn + lc);
            cp_commit();
            cp_wait1();
        } else {
            cp_wait0();
        }
        __syncthreads();

        float S[8][4];
#pragma unroll
        for (int nt = 0; nt < 8; nt++)
#pragma unroll
            for (int r = 0; r < 4; r++) S[nt][r] = 0.f;

        const uint32_t smB = sK[cur];
#pragma unroll
        for (int ks = 0; ks < 4; ks++) {
            uint32_t bf[4][4];
#pragma unroll
            for (int np = 0; np < 4; np++) {
                uint32_t a = smB + 2 * ((np * 16 + (lane & 7) + ((lane >> 4) << 3)) * FSTR
                                        + ks * 16 + ((lane >> 3) & 1) * 8);
                ldsm_x4(bf[np][0], bf[np][1], bf[np][2], bf[np][3], a);
            }
#pragma unroll
            for (int nt = 0; nt < 8; nt++) {
                uint32_t bb[2] = {bf[nt >> 1][(nt & 1) * 2], bf[nt >> 1][(nt & 1) * 2 + 1]};
                mma16816(S[nt], qf[ks], bb);
            }
        }

        // add T2 (contains brr, pre-shifted => contiguous aligned half2); causal mask
        const bool partial = (j0 + 63 > i0 + ML);
        if (!partial) {
#pragma unroll
            for (int nt = 0; nt < 8; nt++) {
                __half2 a0 = *(const __half2*)(Tr0 + j0 + nt * 8);
                __half2 a1 = *(const __half2*)(Tr1 + j0 + nt * 8);
                S[nt][0] += __low2float(a0);  S[nt][1] += __high2float(a0);
                S[nt][2] += __low2float(a1);  S[nt][3] += __high2float(a1);
            }
        } else {
#pragma unroll
            for (int nt = 0; nt < 8; nt++) {
                __half2 a0 = *(const __half2*)(Tr0 + j0 + nt * 8);
                __half2 a1 = *(const __half2*)(Tr1 + j0 + nt * 8);
                const int c0 = j0 + ccb + nt * 8;
                S[nt][0] = (c0     <= rbase + ML)     ? S[nt][0] + __low2float(a0)  : -1e30f;
                S[nt][1] = (c0 + 1 <= rbase + ML)     ? S[nt][1] + __high2float(a0) : -1e30f;
                S[nt][2] = (c0     <= rbase + 8 + ML) ? S[nt][2] + __low2float(a1)  : -1e30f;
                S[nt][3] = (c0 + 1 <= rbase + 8 + ML) ? S[nt][3] + __high2float(a1) : -1e30f;
            }
        }

        // online softmax
        float mx0 = -1e30f, mx1 = -1e30f;
#pragma unroll
        for (int nt = 0; nt < 8; nt++) {
            mx0 = fmaxf(mx0, fmaxf(S[nt][0], S[nt][1]));
            mx1 = fmaxf(mx1, fmaxf(S[nt][2], S[nt][3]));
        }
        mx0 = fmaxf(mx0, __shfl_xor_sync(0xffffffffu, mx0, 1));
        mx0 = fmaxf(mx0, __shfl_xor_sync(0xffffffffu, mx0, 2));
        mx1 = fmaxf(mx1, __shfl_xor_sync(0xffffffffu, mx1, 1));
        mx1 = fmaxf(mx1, __shfl_xor_sync(0xffffffffu, mx1, 2));
        const float mn0 = fmaxf(m0, mx0), mn1 = fmaxf(m1, mx1);
        const float cr0 = __expf(m0 - mn0), cr1 = __expf(m1 - mn1);
        l0 *= cr0; l1 *= cr1;
#pragma unroll
        for (int i = 0; i < 8; i++) {
            O[i][0] *= cr0; O[i][1] *= cr0; O[i][2] *= cr1; O[i][3] *= cr1;
        }
#pragma unroll
        for (int nt = 0; nt < 8; nt++) {
            S[nt][0] = __expf(S[nt][0] - mn0);
            S[nt][1] = __expf(S[nt][1] - mn0);
            S[nt][2] = __expf(S[nt][2] - mn1);
            S[nt][3] = __expf(S[nt][3] - mn1);
            l0 += S[nt][0] + S[nt][1];
            l1 += S[nt][2] + S[nt][3];
        }
        m0 = mn0; m1 = mn1;

        // P @ V  (A-frags repacked from S registers; V B-frags from smem)
        const uint32_t smV = sV[cur];
#pragma unroll
        for (int kp = 0; kp < 4; kp++) {
            uint32_t af[4];
            af[0] = pack_h2(S[2 * kp][0],     S[2 * kp][1]);
            af[1] = pack_h2(S[2 * kp][2],     S[2 * kp][3]);
            af[2] = pack_h2(S[2 * kp + 1][0], S[2 * kp + 1][1]);
            af[3] = pack_h2(S[2 * kp + 1][2], S[2 * kp + 1][3]);
            uint32_t vf[4][4];
#pragma unroll
            for (int np = 0; np < 4; np++) {
                uint32_t a = smV + 2 * ((np * 16 + (lane & 7) + ((lane >> 4) << 3)) * FSTR
                                        + kp * 16 + ((lane >> 3) & 1) * 8);
                ldsm_x4(vf[np][0], vf[np][1], vf[np][2], vf[np][3], a);
            }
#pragma unroll
            for (int nt2 = 0; nt2 < 8; nt2++) {
                uint32_t bb[2] = {vf[nt2 >> 1][(nt2 & 1) * 2], vf[nt2 >> 1][(nt2 & 1) * 2 + 1]};
                mma16816(O[nt2], af, bb);
            }
        }
        __syncthreads();   // compute done before next iteration overwrites old buffer
    }

    // finalize: reduce l over the 4 lanes sharing each row, scale, store fp16
    l0 += __shfl_xor_sync(0xffffffffu, l0, 1);
    l0 += __shfl_xor_sync(0xffffffffu, l0, 2);
    l1 += __shfl_xor_sync(0xffffffffu, l1, 1);
    l1 += __shfl_xor_sync(0xffffffffu, l1, 2);
    const float inv0 = 1.f / l0, inv1 = 1.f / l1;
    __half2* W0 = (__half2*)(g_avh + ((size_t)rbase * BS + b) * DM + n * DH);
    __half2* W1 = (__half2*)(g_avh + ((size_t)(rbase + 8) * BS + b) * DM + n * DH);
    const int cd = lane & 3;
#pragma unroll
    for (int nt2 = 0; nt2 < 8; nt2++) {
        W0[nt2 * 4 + cd] = __floats2half2_rn(O[nt2][0] * inv0, O[nt2][1] * inv0);
        W1[nt2 * 4 + cd] = __floats2half2_rn(O[nt2][2] * inv1, O[nt2][3] * inv1);
    }
}

// ============ LayerNorm ============
__global__ void __launch_bounds__(256) ln_kernel(const float* __restrict__ gamma,
                                                 const float* __restrict__ beta,
                                                 float* __restrict__ out) {
    const int row = blockIdx.x;
    const float* x = g_tmp + (size_t)row * DM;
    float s = 0.f, ss = 0.f;
#pragma unroll
    for (int u = 0; u < 4; u++) {
        float v = x[threadIdx.x + u * 256];
        s += v; ss += v * v;
    }
#pragma unroll
    for (int off = 16; off; off >>= 1) {
        s += __shfl_xor_sync(0xffffffffu, s, off);
        ss += __shfl_xor_sync(0xffffffffu, ss, off);
    }
    __shared__ float sm_s[8], sm_ss[8];
    int wid = threadIdx.x >> 5, lid = threadIdx.x & 31;
    if (lid == 0) { sm_s[wid] = s; sm_ss[wid] = ss; }
    __syncthreads();
    if (threadIdx.x == 0) {
        float a = 0.f, b2 = 0.f;
#pragma unroll
        for (int i2 = 0; i2 < 8; i2++) { a += sm_s[i2]; b2 += sm_ss[i2]; }
        sm_s[0] = a; sm_ss[0] = b2;
    }
    __syncthreads();
    const float mu = sm_s[0] * (1.f / DM);
    const float var = sm_ss[0] * (1.f / DM) - mu * mu;
    const float inv = rsqrtf(var + 1e-5f);
#pragma unroll
    for (int u = 0; u < 4; u++) {
        int c = threadIdx.x + u * 256;
        out[(size_t)row * DM + c] = (x[c] - mu) * inv * gamma[c] + beta[c];
    }
}

// ============ launch ============
extern "C" void kernel_launch(void* const* d_in, const int* in_sizes, int n_in,
                              void* d_out, int out_size) {
    const float* w       = (const float*)d_in[0];   // [1024,4,1024]
    const float* r       = (const float*)d_in[1];   // [2048,1024]
    const float* mems    = (const float*)d_in[2];   // [1024,4,1024]
    // d_in[3] = attn_mask (unused; mask computed analytically: j > i + MLEN)
    const float* qkv_w   = (const float*)d_in[4];   // [3072,1024]
    const float* r_net_w = (const float*)d_in[5];   // [1024,1024]
    const float* o_w     = (const float*)d_in[6];   // [1024,1024]
    const float* rr_bias = (const float*)d_in[7];   // [16,64]
    const float* rw_bias = (const float*)d_in[8];   // [16,64]
    const float* ln_g    = (const float*)d_in[9];   // [1024]
    const float* ln_b    = (const float*)d_in[10];  // [1024]
    float* out = (float*)d_out;

    // round-15 structure; gemm_mma reverted to 2-stage + qkv dead-tile skip
    conv_all<<<15360, 256>>>(mems, w, qkv_w, r, r_net_w, o_w);   // (1) all fp32->fp16
    gemm_mma<1><<<dim3(8, 16), 256>>>(nullptr);                  // (2) R proj
    brr_kernel<<<NH * KL / 256, 256>>>(rr_bias, rw_bias);        // (3) brr
    gemm_mma<0><<<dim3(24, 64), 256>>>(rw_bias);                 // (4) QKV proj  [profiled]
    gemm_mma<3><<<dim3(16, 8, 64), 256>>>(nullptr);              // (5) T2 = shift(Qw@R^T+brr)
    flash_kernel<<<dim3(8, 64), 256>>>();                        // (6) fused S/softmax/PV
    gemm_mma<2><<<dim3(8, 32), 256>>>(w);                        // (7) O proj + residual
    ln_kernel<<<4096, 256>>>(ln_g, ln_b, out);                   // (8) LayerNorm
}